// round 1
// baseline (speedup 1.0000x reference)
#include <cuda_runtime.h>
#include <cstdint>

// Flash attention, tf32 mma.sync baseline.
// B=4, H=16, S=2048, D=64. fp32 in/out, tf32 tensor-core math, fp32 accum.
// One CTA = 128 q rows of one (b,h); loop over 32 kv tiles of 64.

namespace {

constexpr int SEQ = 2048;
constexpr int HD = 64;
constexpr int BM = 128;          // q rows per CTA
constexpr int BN = 64;           // kv rows per iteration
constexpr int THREADS = 256;     // 8 warps, 16 q rows each
constexpr int NKV = SEQ / BN;    // 32

// padded smem strides (floats) chosen for conflict-free fragment LDS
constexpr int QP_STRIDE = 68;    // Q tile, later reused as P tile
constexpr int K_STRIDE  = 68;
constexpr int V_STRIDE  = 72;

constexpr int SK_OFF = BM * QP_STRIDE;               // 8704
constexpr int SV_OFF = SK_OFF + BN * K_STRIDE;       // 13056
constexpr int SMEM_FLOATS = SV_OFF + BN * V_STRIDE;  // 17664 -> 70656 B

__device__ __forceinline__ uint32_t f2tf(float x) {
    uint32_t r;
    asm("cvt.rna.tf32.f32 %0, %1;" : "=r"(r) : "f"(x));
    return r;
}

__device__ __forceinline__ void mma_tf32(float c[4], const uint32_t a[4], const uint32_t b[2]) {
    asm volatile(
        "mma.sync.aligned.m16n8k8.row.col.f32.tf32.tf32.f32 "
        "{%0,%1,%2,%3}, {%4,%5,%6,%7}, {%8,%9}, {%0,%1,%2,%3};\n"
        : "+f"(c[0]), "+f"(c[1]), "+f"(c[2]), "+f"(c[3])
        : "r"(a[0]), "r"(a[1]), "r"(a[2]), "r"(a[3]), "r"(b[0]), "r"(b[1]));
}

__global__ void __launch_bounds__(THREADS)
fa_tf32_kernel(const float* __restrict__ q, const float* __restrict__ k,
               const float* __restrict__ v, float* __restrict__ out)
{
    extern __shared__ float smem[];
    float* sQ = smem;            // [BM][QP_STRIDE]  (becomes P after Q frags hoisted)
    float* sK = smem + SK_OFF;   // [BN][K_STRIDE]
    float* sV = smem + SV_OFF;   // [BN][V_STRIDE]

    const int bh   = blockIdx.y;
    const int qt   = blockIdx.x;
    const int tid  = threadIdx.x;
    const int wid  = tid >> 5;
    const int lane = tid & 31;
    const int g    = lane >> 2;   // mma group id (0..7)
    const int t    = lane & 3;    // thread-in-group (0..3)

    const float scale = 0.125f;   // 1/sqrt(64), folded into Q
    const int base = bh * SEQ * HD;

    // ---- load Q tile (scaled, tf32-rounded) ----
    {
        const float* qg = q + base + qt * BM * HD;
        int r0 = tid >> 4;            // 0..15
        int c  = (tid & 15) * 4;
        #pragma unroll
        for (int i = 0; i < 8; i++) {
            int r = r0 + i * 16;
            float4 val = *reinterpret_cast<const float4*>(qg + r * HD + c);
            uint4 o;
            o.x = f2tf(val.x * scale); o.y = f2tf(val.y * scale);
            o.z = f2tf(val.z * scale); o.w = f2tf(val.w * scale);
            *reinterpret_cast<uint4*>(&sQ[r * QP_STRIDE + c]) = o;
        }
    }
    __syncthreads();

    // ---- hoist Q fragments: 8 k-tiles x 4 regs ----
    const int m0 = wid * 16;
    uint32_t qf[8][4];
    #pragma unroll
    for (int kt = 0; kt < 8; kt++) {
        const float* p = &sQ[(m0 + g) * QP_STRIDE + kt * 8 + t];
        qf[kt][0] = __float_as_uint(p[0]);
        qf[kt][1] = __float_as_uint(p[8 * QP_STRIDE]);
        qf[kt][2] = __float_as_uint(p[4]);
        qf[kt][3] = __float_as_uint(p[8 * QP_STRIDE + 4]);
    }

    float oacc[8][4];
    #pragma unroll
    for (int i = 0; i < 8; i++)
        #pragma unroll
        for (int j = 0; j < 4; j++) oacc[i][j] = 0.f;

    float mrow0 = -1e30f, mrow1 = -1e30f;   // running row max (finite sentinel: no inf-inf NaN)
    float lrow0 = 0.f,    lrow1 = 0.f;      // running row sum

    for (int kvt = 0; kvt < NKV; kvt++) {
        __syncthreads();   // K/V (and P region) fully consumed from prev iter

        // ---- load K,V tiles (tf32-rounded) ----
        {
            const float* kg = k + base + kvt * BN * HD;
            const float* vg = v + base + kvt * BN * HD;
            int r0 = tid >> 4;
            int c  = (tid & 15) * 4;
            #pragma unroll
            for (int i = 0; i < 4; i++) {
                int r = r0 + i * 16;
                float4 kv4 = *reinterpret_cast<const float4*>(kg + r * HD + c);
                uint4 ok;
                ok.x = f2tf(kv4.x); ok.y = f2tf(kv4.y); ok.z = f2tf(kv4.z); ok.w = f2tf(kv4.w);
                *reinterpret_cast<uint4*>(&sK[r * K_STRIDE + c]) = ok;
                float4 vv4 = *reinterpret_cast<const float4*>(vg + r * HD + c);
                uint4 ov;
                ov.x = f2tf(vv4.x); ov.y = f2tf(vv4.y); ov.z = f2tf(vv4.z); ov.w = f2tf(vv4.w);
                *reinterpret_cast<uint4*>(&sV[r * V_STRIDE + c]) = ov;
            }
        }
        __syncthreads();

        // ---- S = (Q*scale) @ K^T  : warp computes 16x64 ----
        float sacc[8][4];
        #pragma unroll
        for (int i = 0; i < 8; i++) {
            sacc[i][0] = 0.f; sacc[i][1] = 0.f; sacc[i][2] = 0.f; sacc[i][3] = 0.f;
        }
        #pragma unroll
        for (int nt = 0; nt < 8; nt++) {
            #pragma unroll
            for (int kt = 0; kt < 8; kt++) {
                uint32_t bf[2];
                const float* kp = &sK[(nt * 8 + g) * K_STRIDE + kt * 8 + t];
                bf[0] = __float_as_uint(kp[0]);
                bf[1] = __float_as_uint(kp[4]);
                mma_tf32(sacc[nt], qf[kt], bf);
            }
        }

        // ---- online softmax ----
        float tmax0 = -1e30f, tmax1 = -1e30f;
        #pragma unroll
        for (int nt = 0; nt < 8; nt++) {
            tmax0 = fmaxf(tmax0, fmaxf(sacc[nt][0], sacc[nt][1]));
            tmax1 = fmaxf(tmax1, fmaxf(sacc[nt][2], sacc[nt][3]));
        }
        tmax0 = fmaxf(tmax0, __shfl_xor_sync(0xffffffffu, tmax0, 1));
        tmax0 = fmaxf(tmax0, __shfl_xor_sync(0xffffffffu, tmax0, 2));
        tmax1 = fmaxf(tmax1, __shfl_xor_sync(0xffffffffu, tmax1, 1));
        tmax1 = fmaxf(tmax1, __shfl_xor_sync(0xffffffffu, tmax1, 2));

        float mn0 = fmaxf(mrow0, tmax0);
        float mn1 = fmaxf(mrow1, tmax1);
        float corr0 = __expf(mrow0 - mn0);
        float corr1 = __expf(mrow1 - mn1);
        mrow0 = mn0; mrow1 = mn1;

        float ts0 = 0.f, ts1 = 0.f;
        const int prow = (m0 + g) * QP_STRIDE;
        #pragma unroll
        for (int nt = 0; nt < 8; nt++) {
            float p00 = __expf(sacc[nt][0] - mn0);
            float p01 = __expf(sacc[nt][1] - mn0);
            float p10 = __expf(sacc[nt][2] - mn1);
            float p11 = __expf(sacc[nt][3] - mn1);
            ts0 += p00 + p01;
            ts1 += p10 + p11;
            float2 lo = make_float2(__uint_as_float(f2tf(p00)), __uint_as_float(f2tf(p01)));
            float2 hi = make_float2(__uint_as_float(f2tf(p10)), __uint_as_float(f2tf(p11)));
            *reinterpret_cast<float2*>(&sQ[prow + nt * 8 + 2 * t]) = lo;
            *reinterpret_cast<float2*>(&sQ[prow + 8 * QP_STRIDE + nt * 8 + 2 * t]) = hi;
        }
        ts0 += __shfl_xor_sync(0xffffffffu, ts0, 1);
        ts0 += __shfl_xor_sync(0xffffffffu, ts0, 2);
        ts1 += __shfl_xor_sync(0xffffffffu, ts1, 1);
        ts1 += __shfl_xor_sync(0xffffffffu, ts1, 2);
        lrow0 = lrow0 * corr0 + ts0;
        lrow1 = lrow1 * corr1 + ts1;

        #pragma unroll
        for (int dt = 0; dt < 8; dt++) {
            oacc[dt][0] *= corr0; oacc[dt][1] *= corr0;
            oacc[dt][2] *= corr1; oacc[dt][3] *= corr1;
        }

        __syncwarp();   // P tile (this warp's own 16 rows) visible across lanes

        // ---- O += P @ V ----
        #pragma unroll
        for (int kt = 0; kt < 8; kt++) {
            uint32_t af[4];
            const float* pp = &sQ[(m0 + g) * QP_STRIDE + kt * 8 + t];
            af[0] = __float_as_uint(pp[0]);
            af[1] = __float_as_uint(pp[8 * QP_STRIDE]);
            af[2] = __float_as_uint(pp[4]);
            af[3] = __float_as_uint(pp[8 * QP_STRIDE + 4]);
            #pragma unroll
            for (int dt = 0; dt < 8; dt++) {
                uint32_t bf[2];
                const float* vp = &sV[(kt * 8 + t) * V_STRIDE + dt * 8 + g];
                bf[0] = __float_as_uint(vp[0]);
                bf[1] = __float_as_uint(vp[4 * V_STRIDE]);
                mma_tf32(oacc[dt], af, bf);
            }
        }
    }

    // ---- epilogue: O /= l, store ----
    float inv0 = 1.f / lrow0;
    float inv1 = 1.f / lrow1;
    float* og = out + base + qt * BM * HD;
    #pragma unroll
    for (int dt = 0; dt < 8; dt++) {
        int c = dt * 8 + 2 * t;
        float2 v0 = make_float2(oacc[dt][0] * inv0, oacc[dt][1] * inv0);
        float2 v1 = make_float2(oacc[dt][2] * inv1, oacc[dt][3] * inv1);
        *reinterpret_cast<float2*>(og + (m0 + g) * HD + c) = v0;
        *reinterpret_cast<float2*>(og + (m0 + g + 8) * HD + c) = v1;
    }
}

}  // namespace

extern "C" void kernel_launch(void* const* d_in, const int* in_sizes, int n_in,
                              void* d_out, int out_size) {
    const float* q = (const float*)d_in[0];
    const float* k = (const float*)d_in[1];
    const float* v = (const float*)d_in[2];
    float* out = (float*)d_out;

    const size_t smem_bytes = SMEM_FLOATS * sizeof(float);  // 70656 B > 48K opt-in
    cudaFuncSetAttribute(fa_tf32_kernel,
                         cudaFuncAttributeMaxDynamicSharedMemorySize, (int)smem_bytes);

    dim3 grid(SEQ / BM, (64));   // 16 q-tiles x (B*H = 64)
    fa_tf32_kernel<<<grid, THREADS, smem_bytes>>>(q, k, v, out);
}